// round 5
// baseline (speedup 1.0000x reference)
#include <cuda_runtime.h>

#define N_BATCH 4
#define C_CH    256
#define C4      (C_CH / 4)        // 64 float4 lanes
#define H_DIM   96
#define W_DIM   96
#define HW      (H_DIM * W_DIM)
#define OUTS    7
#define BINS    (OUTS * OUTS)     // 49
#define G_SAMP  (OUTS * 2)        // 14 sample coords per axis
#define SPATIAL_SCALE 0.0625f
#define TPB     64                // one thread = 4 channels, block = 1 roi

// Scratch: NHWC-transposed features (b, h, w, c)
__device__ float g_featT[(size_t)N_BATCH * HW * C_CH];

// ---------------------------------------------------------------------------
// Transpose (N, C, HW) -> (N, HW, C), 32x32 smem tile.
// ---------------------------------------------------------------------------
__global__ void nchw_to_nhwc(const float* __restrict__ in) {
    __shared__ float tile[32][33];
    const int n   = blockIdx.z;
    const int hw0 = blockIdx.x * 32;
    const int c0  = blockIdx.y * 32;
    const float* inp = in + (size_t)n * C_CH * HW;
    float* op = g_featT + (size_t)n * HW * C_CH;

    const int x = hw0 + threadIdx.x;
#pragma unroll
    for (int j = 0; j < 32; j += 8) {
        const int cc = c0 + threadIdx.y + j;
        tile[threadIdx.y + j][threadIdx.x] = inp[(size_t)cc * HW + x];
    }
    __syncthreads();
    const int cx = c0 + threadIdx.x;
#pragma unroll
    for (int j = 0; j < 32; j += 8) {
        const int hh = hw0 + threadIdx.y + j;
        op[(size_t)hh * C_CH + cx] = tile[threadIdx.x][threadIdx.y + j];
    }
}

// ---------------------------------------------------------------------------
// RoI Align: block = one roi, 64 threads, each thread = 4 channels (float4).
// Offsets premultiplied in float4 units. Stage [c][bin] in dynamic smem,
// writeback is a contiguous float4 copy.
// ---------------------------------------------------------------------------
__global__ __launch_bounds__(TPB) void roi_align_kernel(
    const float* __restrict__ rois,
    float* __restrict__ out)
{
    __shared__ int   s_ylo[G_SAMP], s_yhi[G_SAMP];   // (b*H+y)*W*C4
    __shared__ float s_wyl[G_SAMP], s_wyh[G_SAMP];
    __shared__ int   s_xlo[G_SAMP], s_xhi[G_SAMP];   // x*C4
    __shared__ float s_wxl[G_SAMP], s_wxh[G_SAMP];
    extern __shared__ float stage[];                 // C_CH * BINS floats (49 KB)

    const int k   = blockIdx.x;
    const int tid = threadIdx.x;

    if (tid < 2 * G_SAMP) {
        const int axis = tid / G_SAMP;   // 0 = y, 1 = x
        const int g    = tid % G_SAMP;
        const float* r = rois + (size_t)k * 5;
        const int   b  = (int)r[0];
        const float x1 = r[1] * SPATIAL_SCALE;
        const float y1 = r[2] * SPATIAL_SCALE;
        const float x2 = r[3] * SPATIAL_SCALE;
        const float y2 = r[4] * SPATIAL_SCALE;

        float start, binsz;
        if (axis == 0) { start = y1; binsz = fmaxf(y2 - y1, 1.0f) * (1.0f / OUTS); }
        else           { start = x1; binsz = fmaxf(x2 - x1, 1.0f) * (1.0f / OUTS); }

        const float off   = (float)(g >> 1) + 0.25f + 0.5f * (float)(g & 1);
        const float coord = fmaf(binsz, off, start);
        const bool  valid = (coord >= -1.0f) && (coord <= 96.0f);
        const float cc    = fminf(fmaxf(coord, 0.0f), 95.0f);
        const float lof   = floorf(cc);
        const int   lo    = (int)lof;
        const int   hi    = min(lo + 1, 95);
        const float fr    = cc - lof;
        const float wl    = valid ? 1.0f - fr : 0.0f;
        const float wh    = valid ? fr        : 0.0f;

        if (axis == 0) {
            s_ylo[g] = (b * H_DIM + lo) * W_DIM * C4;
            s_yhi[g] = (b * H_DIM + hi) * W_DIM * C4;
            s_wyl[g] = wl; s_wyh[g] = wh;
        } else {
            s_xlo[g] = lo * C4;
            s_xhi[g] = hi * C4;
            s_wxl[g] = wl; s_wxh[g] = wh;
        }
    }
    __syncthreads();

    const float4* fp = (const float4*)g_featT + tid;   // 4 channels per thread
    const int cb = 4 * tid;                            // first channel owned

#pragma unroll
    for (int i = 0; i < OUTS; i++) {
        const int gy0 = 2 * i, gy1 = 2 * i + 1;
        const int   y0l = s_ylo[gy0], y0h = s_yhi[gy0];
        const int   y1l = s_ylo[gy1], y1h = s_yhi[gy1];
        const float wy0l = s_wyl[gy0], wy0h = s_wyh[gy0];
        const float wy1l = s_wyl[gy1], wy1h = s_wyh[gy1];

#pragma unroll
        for (int j = 0; j < OUTS; j++) {
            float ax = 0.f, ay = 0.f, az = 0.f, aw = 0.f;
#pragma unroll
            for (int sx = 0; sx < 2; sx++) {
                const int gx = 2 * j + sx;
                const int   xl  = s_xlo[gx], xh = s_xhi[gx];
                const float wxl = s_wxl[gx], wxh = s_wxh[gx];

                // sample (gy0, gx): 4 corner weights shared across 4 lanes
                {
                    const float w00 = wy0l * wxl, w01 = wy0l * wxh;
                    const float w10 = wy0h * wxl, w11 = wy0h * wxh;
                    const float4 a00 = __ldg(fp + y0l + xl);
                    const float4 a01 = __ldg(fp + y0l + xh);
                    const float4 a10 = __ldg(fp + y0h + xl);
                    const float4 a11 = __ldg(fp + y0h + xh);
                    ax += w00*a00.x + w01*a01.x + w10*a10.x + w11*a11.x;
                    ay += w00*a00.y + w01*a01.y + w10*a10.y + w11*a11.y;
                    az += w00*a00.z + w01*a01.z + w10*a10.z + w11*a11.z;
                    aw += w00*a00.w + w01*a01.w + w10*a10.w + w11*a11.w;
                }
                // sample (gy1, gx)
                {
                    const float w00 = wy1l * wxl, w01 = wy1l * wxh;
                    const float w10 = wy1h * wxl, w11 = wy1h * wxh;
                    const float4 b00 = __ldg(fp + y1l + xl);
                    const float4 b01 = __ldg(fp + y1l + xh);
                    const float4 b10 = __ldg(fp + y1h + xl);
                    const float4 b11 = __ldg(fp + y1h + xh);
                    ax += w00*b00.x + w01*b01.x + w10*b10.x + w11*b11.x;
                    ay += w00*b00.y + w01*b01.y + w10*b10.y + w11*b11.y;
                    az += w00*b00.z + w01*b01.z + w10*b10.z + w11*b11.z;
                    aw += w00*b00.w + w01*b01.w + w10*b10.w + w11*b11.w;
                }
            }
            const int bb = i * OUTS + j;
            // stage layout matches output: float index c*BINS + bin
            stage[(cb + 0) * BINS + bb] = ax * 0.25f;
            stage[(cb + 1) * BINS + bb] = ay * 0.25f;
            stage[(cb + 2) * BINS + bb] = az * 0.25f;
            stage[(cb + 3) * BINS + bb] = aw * 0.25f;
        }
    }
    __syncthreads();

    // Contiguous float4 writeback: block owns 256*49 consecutive floats.
    float4* o4 = (float4*)(out + (size_t)k * C_CH * BINS);
    const float4* s4 = (const float4*)stage;
#pragma unroll
    for (int t = tid; t < C_CH * BINS / 4; t += TPB)
        o4[t] = s4[t];
}

extern "C" void kernel_launch(void* const* d_in, const int* in_sizes, int n_in,
                              void* d_out, int out_size) {
    const float* features = (const float*)d_in[0];
    const float* rois     = (const float*)d_in[1];
    float* out            = (float*)d_out;
    const int K = in_sizes[1] / 5;

    const int stage_bytes = C_CH * BINS * (int)sizeof(float);  // 50176
    cudaFuncSetAttribute(roi_align_kernel,
                         cudaFuncAttributeMaxDynamicSharedMemorySize, stage_bytes);

    // 1) NCHW -> NHWC transpose into scratch
    nchw_to_nhwc<<<dim3(HW / 32, C_CH / 32, N_BATCH), dim3(32, 8)>>>(features);

    // 2) RoI Align gather, float4 per thread, fully coalesced
    roi_align_kernel<<<K, TPB, stage_bytes>>>(rois, out);
}

// round 6
// speedup vs baseline: 1.5469x; 1.5469x over previous
#include <cuda_runtime.h>

#define N_BATCH 4
#define C_CH    256
#define C2      (C_CH / 2)        // 128 float2 lanes
#define H_DIM   96
#define W_DIM   96
#define HW      (H_DIM * W_DIM)
#define OUTS    7
#define BINS    (OUTS * OUTS)     // 49
#define G_SAMP  (OUTS * 2)
#define SPATIAL_SCALE 0.0625f
#define TPB     128               // thread = 2 channels, block = 1 roi

#define NB_A    28                // bins in phase A (i = 0..3)
#define NB_B    21                // bins in phase B (i = 4..6)
#define SA      29                // padded stride (odd -> 2-way STS max)
#define SB      21                // already odd

// Scratch: NHWC-transposed features (b, h, w, c)
__device__ float g_featT[(size_t)N_BATCH * HW * C_CH];

// ---------------------------------------------------------------------------
// Transpose (N, C, HW) -> (N, HW, C), 32x32 smem tile (proven, ~16us).
// ---------------------------------------------------------------------------
__global__ void nchw_to_nhwc(const float* __restrict__ in) {
    __shared__ float tile[32][33];
    const int n   = blockIdx.z;
    const int hw0 = blockIdx.x * 32;
    const int c0  = blockIdx.y * 32;
    const float* inp = in + (size_t)n * C_CH * HW;
    float* op = g_featT + (size_t)n * HW * C_CH;

    const int x = hw0 + threadIdx.x;
#pragma unroll
    for (int j = 0; j < 32; j += 8) {
        const int cc = c0 + threadIdx.y + j;
        tile[threadIdx.y + j][threadIdx.x] = inp[(size_t)cc * HW + x];
    }
    __syncthreads();
    const int cx = c0 + threadIdx.x;
#pragma unroll
    for (int j = 0; j < 32; j += 8) {
        const int hh = hw0 + threadIdx.y + j;
        op[(size_t)hh * C_CH + cx] = tile[threadIdx.x][threadIdx.y + j];
    }
}

// ---------------------------------------------------------------------------
// RoI Align: block = 1 roi, 128 threads, thread = 2 channels (float2 loads).
// Two-phase smem stage (~29KB) -> ~7 CTAs/SM, coalesced-ish writeback.
// ---------------------------------------------------------------------------
__global__ __launch_bounds__(TPB) void roi_align_kernel(
    const float* __restrict__ rois,
    float* __restrict__ out)
{
    __shared__ int   s_ylo[G_SAMP], s_yhi[G_SAMP];   // (b*H+y)*W*C2
    __shared__ float s_wyl[G_SAMP], s_wyh[G_SAMP];
    __shared__ int   s_xlo[G_SAMP], s_xhi[G_SAMP];   // x*C2
    __shared__ float s_wxl[G_SAMP], s_wxh[G_SAMP];
    __shared__ float stage[C_CH * SA];               // 29696 B (phase B fits too)

    const int k   = blockIdx.x;
    const int tid = threadIdx.x;

    if (tid < 2 * G_SAMP) {
        const int axis = tid / G_SAMP;   // 0 = y, 1 = x
        const int g    = tid % G_SAMP;
        const float* r = rois + (size_t)k * 5;
        const int   b  = (int)r[0];
        const float x1 = r[1] * SPATIAL_SCALE;
        const float y1 = r[2] * SPATIAL_SCALE;
        const float x2 = r[3] * SPATIAL_SCALE;
        const float y2 = r[4] * SPATIAL_SCALE;

        float start, binsz;
        if (axis == 0) { start = y1; binsz = fmaxf(y2 - y1, 1.0f) * (1.0f / OUTS); }
        else           { start = x1; binsz = fmaxf(x2 - x1, 1.0f) * (1.0f / OUTS); }

        const float off   = (float)(g >> 1) + 0.25f + 0.5f * (float)(g & 1);
        const float coord = fmaf(binsz, off, start);
        const bool  valid = (coord >= -1.0f) && (coord <= 96.0f);
        const float cc    = fminf(fmaxf(coord, 0.0f), 95.0f);
        const float lof   = floorf(cc);
        const int   lo    = (int)lof;
        const int   hi    = min(lo + 1, 95);
        const float fr    = cc - lof;
        const float wl    = valid ? 1.0f - fr : 0.0f;
        const float wh    = valid ? fr        : 0.0f;

        if (axis == 0) {
            s_ylo[g] = (b * H_DIM + lo) * W_DIM * C2;
            s_yhi[g] = (b * H_DIM + hi) * W_DIM * C2;
            s_wyl[g] = wl; s_wyh[g] = wh;
        } else {
            s_xlo[g] = lo * C2;
            s_xhi[g] = hi * C2;
            s_wxl[g] = wl; s_wxh[g] = wh;
        }
    }
    __syncthreads();

    const float2* fp = (const float2*)g_featT + tid;   // 2 channels per thread
    const int c0 = 2 * tid;
    float* obase = out + (size_t)k * C_CH * BINS;

    // One bin-row of work: 8 float2 gathers + bilinear combine for (i, j).
#define DO_BIN(i, j, STRIDE, LB)                                              \
    {                                                                         \
        const int gy0 = 2 * (i), gy1 = 2 * (i) + 1;                           \
        const int   y0l = s_ylo[gy0], y0h = s_yhi[gy0];                       \
        const int   y1l = s_ylo[gy1], y1h = s_yhi[gy1];                       \
        const float wy0l = s_wyl[gy0], wy0h = s_wyh[gy0];                     \
        const float wy1l = s_wyl[gy1], wy1h = s_wyh[gy1];                     \
        float ax = 0.f, ay = 0.f;                                             \
        _Pragma("unroll")                                                     \
        for (int sx = 0; sx < 2; sx++) {                                      \
            const int gx = 2 * (j) + sx;                                      \
            const int   xl  = s_xlo[gx], xh = s_xhi[gx];                      \
            const float wxl = s_wxl[gx], wxh = s_wxh[gx];                     \
            {                                                                 \
                const float w00 = wy0l * wxl, w01 = wy0l * wxh;               \
                const float w10 = wy0h * wxl, w11 = wy0h * wxh;               \
                const float2 a00 = __ldg(fp + y0l + xl);                      \
                const float2 a01 = __ldg(fp + y0l + xh);                      \
                const float2 a10 = __ldg(fp + y0h + xl);                      \
                const float2 a11 = __ldg(fp + y0h + xh);                      \
                ax += w00*a00.x + w01*a01.x + w10*a10.x + w11*a11.x;          \
                ay += w00*a00.y + w01*a01.y + w10*a10.y + w11*a11.y;          \
            }                                                                 \
            {                                                                 \
                const float w00 = wy1l * wxl, w01 = wy1l * wxh;               \
                const float w10 = wy1h * wxl, w11 = wy1h * wxh;               \
                const float2 b00 = __ldg(fp + y1l + xl);                      \
                const float2 b01 = __ldg(fp + y1l + xh);                      \
                const float2 b10 = __ldg(fp + y1h + xl);                      \
                const float2 b11 = __ldg(fp + y1h + xh);                      \
                ax += w00*b00.x + w01*b01.x + w10*b10.x + w11*b11.x;          \
                ay += w00*b00.y + w01*b01.y + w10*b10.y + w11*b11.y;          \
            }                                                                 \
        }                                                                     \
        stage[(c0    ) * (STRIDE) + (LB)] = ax * 0.25f;                       \
        stage[(c0 + 1) * (STRIDE) + (LB)] = ay * 0.25f;                       \
    }

    // ---- Phase A: bins 0..27 (i = 0..3) ----
#pragma unroll
    for (int i = 0; i < 4; i++)
#pragma unroll
        for (int j = 0; j < OUTS; j++)
            DO_BIN(i, j, SA, i * OUTS + j)
    __syncthreads();
#pragma unroll
    for (int t = tid; t < C_CH * NB_A; t += TPB) {
        const int c  = t / NB_A;
        const int lb = t - c * NB_A;
        obase[c * BINS + lb] = stage[c * SA + lb];
    }
    __syncthreads();

    // ---- Phase B: bins 28..48 (i = 4..6) ----
#pragma unroll
    for (int i = 4; i < OUTS; i++)
#pragma unroll
        for (int j = 0; j < OUTS; j++)
            DO_BIN(i, j, SB, (i - 4) * OUTS + j)
    __syncthreads();
#pragma unroll
    for (int t = tid; t < C_CH * NB_B; t += TPB) {
        const int c  = t / NB_B;
        const int lb = t - c * NB_B;
        obase[c * BINS + NB_A + lb] = stage[c * SB + lb];
    }
#undef DO_BIN
}

extern "C" void kernel_launch(void* const* d_in, const int* in_sizes, int n_in,
                              void* d_out, int out_size) {
    const float* features = (const float*)d_in[0];
    const float* rois     = (const float*)d_in[1];
    float* out            = (float*)d_out;
    const int K = in_sizes[1] / 5;

    // 1) NCHW -> NHWC transpose into scratch
    nchw_to_nhwc<<<dim3(HW / 32, C_CH / 32, N_BATCH), dim3(32, 8)>>>(features);

    // 2) RoI Align gather, float2 per thread, two-phase staged writeback
    roi_align_kernel<<<K, TPB>>>(rois, out);
}

// round 8
// speedup vs baseline: 1.7271x; 1.1164x over previous
#include <cuda_runtime.h>

#define N_BATCH 4
#define C_CH    256
#define C2      (C_CH / 2)        // 128 float2 lanes
#define H_DIM   96
#define W_DIM   96
#define HW      (H_DIM * W_DIM)
#define OUTS    7
#define BINS    (OUTS * OUTS)     // 49
#define G_SAMP  (OUTS * 2)
#define SPATIAL_SCALE 0.0625f
#define TPB     128               // thread = 2 channels, block = 1 roi

#define NB_A    28                // bins in phase A (i = 0..3)
#define NB_B    21                // bins in phase B (i = 4..6)
#define SA      29                // padded stride (odd -> 2-way STS max)
#define SB      21                // already odd

// Scratch: NHWC-transposed features (b, h, w, c)
__device__ float g_featT[(size_t)N_BATCH * HW * C_CH];

// ---------------------------------------------------------------------------
// Transpose (N, C, HW) -> (N, HW, C), 32x32 smem tile (~11-16us, near BW floor)
// ---------------------------------------------------------------------------
__global__ void nchw_to_nhwc(const float* __restrict__ in) {
    __shared__ float tile[32][33];
    const int n   = blockIdx.z;
    const int hw0 = blockIdx.x * 32;
    const int c0  = blockIdx.y * 32;
    const float* inp = in + (size_t)n * C_CH * HW;
    float* op = g_featT + (size_t)n * HW * C_CH;

    const int x = hw0 + threadIdx.x;
#pragma unroll
    for (int j = 0; j < 32; j += 8) {
        const int cc = c0 + threadIdx.y + j;
        tile[threadIdx.y + j][threadIdx.x] = inp[(size_t)cc * HW + x];
    }
    __syncthreads();
    const int cx = c0 + threadIdx.x;
#pragma unroll
    for (int j = 0; j < 32; j += 8) {
        const int hh = hw0 + threadIdx.y + j;
        op[(size_t)hh * C_CH + cx] = tile[threadIdx.x][threadIdx.y + j];
    }
}

// ---------------------------------------------------------------------------
// RoI Align: block = 1 roi, 128 threads, thread = 2 channels (float2 loads).
// __launch_bounds__(128, 8) caps regs at 64 -> 7 CTAs/SM (smem-limited),
// restoring R4-level occupancy with half the instruction stream.
// ---------------------------------------------------------------------------
__global__ __launch_bounds__(TPB, 8) void roi_align_kernel(
    const float* __restrict__ rois,
    float* __restrict__ out)
{
    __shared__ int   s_ylo[G_SAMP], s_yhi[G_SAMP];   // (b*H+y)*W*C2
    __shared__ float s_wyl[G_SAMP], s_wyh[G_SAMP];
    __shared__ int   s_xlo[G_SAMP], s_xhi[G_SAMP];   // x*C2
    __shared__ float s_wxl[G_SAMP], s_wxh[G_SAMP];
    __shared__ float stage[C_CH * SA];               // 29696 B

    const int k   = blockIdx.x;
    const int tid = threadIdx.x;

    if (tid < 2 * G_SAMP) {
        const int axis = tid / G_SAMP;   // 0 = y, 1 = x
        const int g    = tid % G_SAMP;
        const float* r = rois + (size_t)k * 5;
        const int   b  = (int)r[0];
        const float x1 = r[1] * SPATIAL_SCALE;
        const float y1 = r[2] * SPATIAL_SCALE;
        const float x2 = r[3] * SPATIAL_SCALE;
        const float y2 = r[4] * SPATIAL_SCALE;

        float start, binsz;
        if (axis == 0) { start = y1; binsz = fmaxf(y2 - y1, 1.0f) * (1.0f / OUTS); }
        else           { start = x1; binsz = fmaxf(x2 - x1, 1.0f) * (1.0f / OUTS); }

        const float off   = (float)(g >> 1) + 0.25f + 0.5f * (float)(g & 1);
        const float coord = fmaf(binsz, off, start);
        const bool  valid = (coord >= -1.0f) && (coord <= 96.0f);
        const float cc    = fminf(fmaxf(coord, 0.0f), 95.0f);
        const float lof   = floorf(cc);
        const int   lo    = (int)lof;
        const int   hi    = min(lo + 1, 95);
        const float fr    = cc - lof;
        const float wl    = valid ? 1.0f - fr : 0.0f;
        const float wh    = valid ? fr        : 0.0f;

        if (axis == 0) {
            s_ylo[g] = (b * H_DIM + lo) * W_DIM * C2;
            s_yhi[g] = (b * H_DIM + hi) * W_DIM * C2;
            s_wyl[g] = wl; s_wyh[g] = wh;
        } else {
            s_xlo[g] = lo * C2;
            s_xhi[g] = hi * C2;
            s_wxl[g] = wl; s_wxh[g] = wh;
        }
    }
    __syncthreads();

    const float2* fp = (const float2*)g_featT + tid;   // 2 channels per thread
    const int c0 = 2 * tid;
    float* obase = out + (size_t)k * C_CH * BINS;

    // One bin: 8 float2 gathers + bilinear combine for (i, j).
#define DO_BIN(i, j, STRIDE, LB)                                              \
    {                                                                         \
        const int gy0 = 2 * (i), gy1 = 2 * (i) + 1;                           \
        const int   y0l = s_ylo[gy0], y0h = s_yhi[gy0];                       \
        const int   y1l = s_ylo[gy1], y1h = s_yhi[gy1];                       \
        const float wy0l = s_wyl[gy0], wy0h = s_wyh[gy0];                     \
        const float wy1l = s_wyl[gy1], wy1h = s_wyh[gy1];                     \
        float ax = 0.f, ay = 0.f;                                             \
        _Pragma("unroll")                                                     \
        for (int sx = 0; sx < 2; sx++) {                                      \
            const int gx = 2 * (j) + sx;                                      \
            const int   xl  = s_xlo[gx], xh = s_xhi[gx];                      \
            const float wxl = s_wxl[gx], wxh = s_wxh[gx];                     \
            {                                                                 \
                const float w00 = wy0l * wxl, w01 = wy0l * wxh;               \
                const float w10 = wy0h * wxl, w11 = wy0h * wxh;               \
                const float2 a00 = __ldg(fp + y0l + xl);                      \
                const float2 a01 = __ldg(fp + y0l + xh);                      \
                const float2 a10 = __ldg(fp + y0h + xl);                      \
                const float2 a11 = __ldg(fp + y0h + xh);                      \
                ax += w00*a00.x + w01*a01.x + w10*a10.x + w11*a11.x;          \
                ay += w00*a00.y + w01*a01.y + w10*a10.y + w11*a11.y;          \
            }                                                                 \
            {                                                                 \
                const float w00 = wy1l * wxl, w01 = wy1l * wxh;               \
                const float w10 = wy1h * wxl, w11 = wy1h * wxh;               \
                const float2 b00 = __ldg(fp + y1l + xl);                      \
                const float2 b01 = __ldg(fp + y1l + xh);                      \
                const float2 b10 = __ldg(fp + y1h + xl);                      \
                const float2 b11 = __ldg(fp + y1h + xh);                      \
                ax += w00*b00.x + w01*b01.x + w10*b10.x + w11*b11.x;          \
                ay += w00*b00.y + w01*b01.y + w10*b10.y + w11*b11.y;          \
            }                                                                 \
        }                                                                     \
        stage[(c0    ) * (STRIDE) + (LB)] = ax * 0.25f;                       \
        stage[(c0 + 1) * (STRIDE) + (LB)] = ay * 0.25f;                       \
    }

    // ---- Phase A: bins 0..27 (i = 0..3) ----
#pragma unroll
    for (int i = 0; i < 4; i++)
#pragma unroll
        for (int j = 0; j < OUTS; j++)
            DO_BIN(i, j, SA, i * OUTS + j)
    __syncthreads();
#pragma unroll
    for (int t = tid; t < C_CH * NB_A; t += TPB) {
        const int c  = t / NB_A;
        const int lb = t - c * NB_A;
        obase[c * BINS + lb] = stage[c * SA + lb];
    }
    __syncthreads();

    // ---- Phase B: bins 28..48 (i = 4..6) ----
#pragma unroll
    for (int i = 4; i < OUTS; i++)
#pragma unroll
        for (int j = 0; j < OUTS; j++)
            DO_BIN(i, j, SB, (i - 4) * OUTS + j)
    __syncthreads();
#pragma unroll
    for (int t = tid; t < C_CH * NB_B; t += TPB) {
        const int c  = t / NB_B;
        const int lb = t - c * NB_B;
        obase[c * BINS + NB_A + lb] = stage[c * SB + lb];
    }
#undef DO_BIN
}

extern "C" void kernel_launch(void* const* d_in, const int* in_sizes, int n_in,
                              void* d_out, int out_size) {
    const float* features = (const float*)d_in[0];
    const float* rois     = (const float*)d_in[1];
    float* out            = (float*)d_out;
    const int K = in_sizes[1] / 5;

    // 1) NCHW -> NHWC transpose into scratch
    nchw_to_nhwc<<<dim3(HW / 32, C_CH / 32, N_BATCH), dim3(32, 8)>>>(features);

    // 2) RoI Align gather, float2 per thread, reg-capped for occupancy
    roi_align_kernel<<<K, TPB>>>(rois, out);
}

// round 11
// speedup vs baseline: 2.0375x; 1.1798x over previous
#include <cuda_runtime.h>

#define N_BATCH 4
#define C_CH    256
#define C2      (C_CH / 2)        // 128 float2 lanes
#define H_DIM   96
#define W_DIM   96
#define HW      (H_DIM * W_DIM)
#define OUTS    7
#define BINS    (OUTS * OUTS)     // 49
#define NSAMP   (BINS * 4)        // 196 bilinear samples per roi
#define G_SAMP  (OUTS * 2)
#define SPATIAL_SCALE 0.0625f
#define TPB     128               // thread = 2 channels, block = 1 roi

#define SSTR    17                // stage stride (odd -> low STS conflict)
#define NB_A    17                // bins 0..16
#define NB_B    16                // bins 17..32
#define NB_C    16                // bins 33..48

// Scratch: NHWC-transposed features (b, h, w, c)
__device__ float g_featT[(size_t)N_BATCH * HW * C_CH];

// ---------------------------------------------------------------------------
// Transpose (N, C, HW) -> (N, HW, C), 32x32 smem tile.
// ---------------------------------------------------------------------------
__global__ void nchw_to_nhwc(const float* __restrict__ in) {
    __shared__ float tile[32][33];
    const int n   = blockIdx.z;
    const int hw0 = blockIdx.x * 32;
    const int c0  = blockIdx.y * 32;
    const float* inp = in + (size_t)n * C_CH * HW;
    float* op = g_featT + (size_t)n * HW * C_CH;

    const int x = hw0 + threadIdx.x;
#pragma unroll
    for (int j = 0; j < 32; j += 8) {
        const int cc = c0 + threadIdx.y + j;
        tile[threadIdx.y + j][threadIdx.x] = inp[(size_t)cc * HW + x];
    }
    __syncthreads();
    const int cx = c0 + threadIdx.x;
#pragma unroll
    for (int j = 0; j < 32; j += 8) {
        const int hh = hw0 + threadIdx.y + j;
        op[(size_t)hh * C_CH + cx] = tile[threadIdx.x][threadIdx.y + j];
    }
}

// ---------------------------------------------------------------------------
// RoI Align: block = 1 roi, 128 threads, thread = 2 channels.
// Per-roi precomputed sample table (combined corner offsets + 0.25-folded
// weights) makes the inner loop 2 LDS.128 + 4 LDG.64 + 8 FFMA per sample.
// Three-phase stride-17 stage -> ~24 KB smem -> 8 CTAs/SM at 64 regs.
// ---------------------------------------------------------------------------
__global__ __launch_bounds__(TPB, 8) void roi_align_kernel(
    const float* __restrict__ rois,
    float* __restrict__ out)
{
    __shared__ int   s_ylo[G_SAMP], s_yhi[G_SAMP];   // (b*H+y)*W*C2
    __shared__ float s_wyl[G_SAMP], s_wyh[G_SAMP];
    __shared__ int   s_xlo[G_SAMP], s_xhi[G_SAMP];   // x*C2
    __shared__ float s_wxl[G_SAMP], s_wxh[G_SAMP];
    __shared__ int4   s_off[NSAMP];                  // 4 corner offsets / sample
    __shared__ float4 s_w[NSAMP];                    // 4 corner weights * 0.25
    __shared__ float  stage[C_CH * SSTR];            // 17408 B

    const int k   = blockIdx.x;
    const int tid = threadIdx.x;

    // ---- 1D interpolation tables (28 threads) ----
    if (tid < 2 * G_SAMP) {
        const int axis = tid / G_SAMP;   // 0 = y, 1 = x
        const int g    = tid % G_SAMP;
        const float* r = rois + (size_t)k * 5;
        const int   b  = (int)r[0];
        const float x1 = r[1] * SPATIAL_SCALE;
        const float y1 = r[2] * SPATIAL_SCALE;
        const float x2 = r[3] * SPATIAL_SCALE;
        const float y2 = r[4] * SPATIAL_SCALE;

        float start, binsz;
        if (axis == 0) { start = y1; binsz = fmaxf(y2 - y1, 1.0f) * (1.0f / OUTS); }
        else           { start = x1; binsz = fmaxf(x2 - x1, 1.0f) * (1.0f / OUTS); }

        const float off   = (float)(g >> 1) + 0.25f + 0.5f * (float)(g & 1);
        const float coord = fmaf(binsz, off, start);
        const bool  valid = (coord >= -1.0f) && (coord <= 96.0f);
        const float cc    = fminf(fmaxf(coord, 0.0f), 95.0f);
        const float lof   = floorf(cc);
        const int   lo    = (int)lof;
        const int   hi    = min(lo + 1, 95);
        const float fr    = cc - lof;
        const float wl    = valid ? 1.0f - fr : 0.0f;
        const float wh    = valid ? fr        : 0.0f;

        if (axis == 0) {
            s_ylo[g] = (b * H_DIM + lo) * W_DIM * C2;
            s_yhi[g] = (b * H_DIM + hi) * W_DIM * C2;
            s_wyl[g] = wl; s_wyh[g] = wh;
        } else {
            s_xlo[g] = lo * C2;
            s_xhi[g] = hi * C2;
            s_wxl[g] = wl; s_wxh[g] = wh;
        }
    }
    __syncthreads();

    // ---- Per-sample combined tables: offsets + pre-scaled weights ----
    // sample s = bin*4 + (sy*2 + sx), bin = i*7 + j
    for (int s = tid; s < NSAMP; s += TPB) {
        const int bin = s >> 2;
        const int sub = s & 3;
        const int i   = bin / OUTS;
        const int j   = bin - i * OUTS;
        const int gy  = 2 * i + (sub >> 1);
        const int gx  = 2 * j + (sub & 1);
        const int yl  = s_ylo[gy], yh = s_yhi[gy];
        const int xl  = s_xlo[gx], xh = s_xhi[gx];
        const float wyl = s_wyl[gy], wyh = s_wyh[gy];
        const float wxl = s_wxl[gx], wxh = s_wxh[gx];
        s_off[s] = make_int4(yl + xl, yl + xh, yh + xl, yh + xh);
        s_w[s]   = make_float4(0.25f * wyl * wxl, 0.25f * wyl * wxh,
                               0.25f * wyh * wxl, 0.25f * wyh * wxh);
    }
    __syncthreads();

    const float2* fp = (const float2*)g_featT + tid;   // 2 channels per thread
    const int c0 = 2 * tid;
    float* obase = out + (size_t)k * C_CH * BINS;

#define DO_PHASE(B0, NB)                                                      \
    {                                                                         \
        for (int b = (B0); b < (B0) + (NB); b++) {                            \
            float ax = 0.f, ay = 0.f;                                         \
            _Pragma("unroll")                                                 \
            for (int sub = 0; sub < 4; sub++) {                               \
                const int4   o = s_off[b * 4 + sub];                          \
                const float4 w = s_w[b * 4 + sub];                            \
                const float2 v0 = __ldg(fp + o.x);                            \
                const float2 v1 = __ldg(fp + o.y);                            \
                const float2 v2 = __ldg(fp + o.z);                            \
                const float2 v3 = __ldg(fp + o.w);                            \
                ax += w.x * v0.x + w.y * v1.x + w.z * v2.x + w.w * v3.x;      \
                ay += w.x * v0.y + w.y * v1.y + w.z * v2.y + w.w * v3.y;      \
            }                                                                 \
            stage[(c0    ) * SSTR + (b - (B0))] = ax;                         \
            stage[(c0 + 1) * SSTR + (b - (B0))] = ay;                         \
        }                                                                     \
        __syncthreads();                                                      \
        for (int t = tid; t < C_CH * (NB); t += TPB) {                        \
            const int c  = t / (NB);                                          \
            const int lb = t - c * (NB);                                      \
            obase[c * BINS + (B0) + lb] = stage[c * SSTR + lb];               \
        }                                                                     \
        __syncthreads();                                                      \
    }

    DO_PHASE(0, NB_A)
    DO_PHASE(NB_A, NB_B)
    DO_PHASE(NB_A + NB_B, NB_C)
#undef DO_PHASE
}

extern "C" void kernel_launch(void* const* d_in, const int* in_sizes, int n_in,
                              void* d_out, int out_size) {
    const float* features = (const float*)d_in[0];
    const float* rois     = (const float*)d_in[1];
    float* out            = (float*)d_out;
    const int K = in_sizes[1] / 5;

    // 1) NCHW -> NHWC transpose into scratch
    nchw_to_nhwc<<<dim3(HW / 32, C_CH / 32, N_BATCH), dim3(32, 8)>>>(features);

    // 2) RoI Align gather with per-roi precomputed sample tables
    roi_align_kernel<<<K, TPB>>>(rois, out);
}